// round 3
// baseline (speedup 1.0000x reference)
#include <cuda_runtime.h>
#include <cstdint>

#define DM   1024
#define DS   256
#define BATCH 8
#define SEQ  2048
#define LCH  16
#define NCH  (SEQ/LCH)      /* 128 */
#define MTOT (BATCH*SEQ)    /* 16384 */

// ---------------- device scratch (no dynamic allocation allowed) -----------
__device__ float g_M [DS*DS];
__device__ float g_T0[DS*DS];
__device__ float g_T1[DS*DS];
__device__ float g_Ad[DS*DS];
__device__ float g_P [7][DS*DS];          // A_d^(16*2^s), s=0..6
__device__ float g_u [MTOT*DS];           // rows = b*SEQ + t
__device__ float g_f [BATCH*NCH*DS];      // rows = b*NCH + c (chunk-local finals)
__device__ float g_g [BATCH*NCH*DS];      // KS ping-pong
__device__ float g_hs[MTOT*DS];           // full hidden states

// ---------------- packed f32x2 helpers -------------------------------------
__device__ __forceinline__ unsigned long long pk2(float a, float b){
    unsigned long long r;
    asm("mov.b64 %0, {%1,%2};" : "=l"(r) : "f"(a), "f"(b));
    return r;
}
__device__ __forceinline__ void unpk2(unsigned long long v, float& a, float& b){
    asm("mov.b64 {%0,%1}, %2;" : "=f"(a), "=f"(b) : "l"(v));
}
__device__ __forceinline__ unsigned long long ffma2(unsigned long long a,
                                                    unsigned long long b,
                                                    unsigned long long c){
    unsigned long long d;
    asm("fma.rn.f32x2 %0, %1, %2, %3;" : "=l"(d) : "l"(a), "l"(b), "l"(c));
    return d;
}

// ---------------- init: M = 0.1*A ; Ad = I + M ; T0 = M --------------------
__global__ void k_init(const float* __restrict__ A){
    int i = blockIdx.x*256 + threadIdx.x;
    float m = 0.1f * A[i];
    g_M[i]  = m;
    g_T0[i] = m;
    int r = i >> 8, c = i & 255;
    g_Ad[i] = m + (r == c ? 1.0f : 0.0f);
}

// ---------------- selector for small matrices -------------------------------
__device__ __forceinline__ float* selmat(int s){
    switch(s){
        case 0: return g_M;
        case 1: return g_T0;
        case 2: return g_T1;
        case 3: return g_Ad;
        default: return g_P[s-4];
    }
}

// ---------------- 256x256x256 GEMM: C = alpha*(A@B), optional g_Ad += ------
__global__ void __launch_bounds__(256) k_mm256(int sa, int sb, int sc,
                                               float alpha, int accAd){
    const float* A  = selmat(sa);
    const float* Bm = selmat(sb);
    float*       Cm = selmat(sc);
    __shared__ float As[32][33];
    __shared__ float Bs[32][33];
    int tx = threadIdx.x & 31, ty = threadIdx.x >> 5;
    int bi = blockIdx.y*32, bj = blockIdx.x*32;
    float acc[4] = {0.f,0.f,0.f,0.f};
    for(int k0 = 0; k0 < DS; k0 += 32){
        #pragma unroll
        for(int r = ty; r < 32; r += 8){
            As[r][tx] = A [(bi+r)*DS + k0 + tx];
            Bs[r][tx] = Bm[(k0+r)*DS + bj + tx];
        }
        __syncthreads();
        #pragma unroll
        for(int k = 0; k < 32; k++){
            float b = Bs[k][tx];
            #pragma unroll
            for(int i = 0; i < 4; i++) acc[i] += As[ty*4+i][k] * b;
        }
        __syncthreads();
    }
    #pragma unroll
    for(int i = 0; i < 4; i++){
        int idx = (bi + ty*4 + i)*DS + bj + tx;
        float v = alpha * acc[i];
        Cm[idx] = v;
        if(accAd) g_Ad[idx] += v;
    }
}

// ---------------- fold h0 into u[.,0,:]: u0 += h0 @ Ad ----------------------
__global__ void k_h0(const float* __restrict__ h0){
    int j = threadIdx.x;
    for(int b = 0; b < BATCH; b++){
        float acc = 0.f;
        for(int i = 0; i < DS; i++) acc += h0[b*DS+i] * g_Ad[i*DS+j];
        g_u[(size_t)b*SEQ*DS + j] += acc;
    }
}

// ---------------- big SGEMM (f32x2): C[M,N] = A@B (+ X*D epilogue) ----------
template<int KDIM, int NDIM, bool EPI>
__global__ void __launch_bounds__(256,2) k_gemm(const float* __restrict__ A,
                                                const float* __restrict__ B,
                                                float* __restrict__ Cout,
                                                const float* __restrict__ X,
                                                const float* __restrict__ Dv){
    const int BM = 128, BN = 64, BK = 16, ASD = 132, BSD = 68;
    __shared__ float As[2][BK*ASD];
    __shared__ float Bs[2][BK*BSD];
    int tid = threadIdx.x;
    int tx = tid & 15, ty = tid >> 4;         // 16 x 16
    int row0 = blockIdx.y * BM;
    int col0 = blockIdx.x * BN;
    int mBase = ty * 8;
    int nBase = tx * 4;

    int a_k4 = tid & 3, a_m = tid >> 2;
    const float* Ap0 = A + (size_t)(row0 + a_m)*KDIM + a_k4*4;
    int b_k = tid >> 4, b_n = (tid & 15)*4;
    const float* Bp0 = B + (size_t)b_k*NDIM + col0 + b_n;

    float4 ra0 = *(const float4*)(Ap0);
    float4 ra1 = *(const float4*)(Ap0 + (size_t)64*KDIM);
    float4 rb  = *(const float4*)(Bp0);

    #pragma unroll
    for(int jj = 0; jj < 4; jj++){
        As[0][(a_k4*4+jj)*ASD + a_m     ] = ((const float*)&ra0)[jj];
        As[0][(a_k4*4+jj)*ASD + a_m + 64] = ((const float*)&ra1)[jj];
    }
    *(float4*)&Bs[0][b_k*BSD + b_n] = rb;
    __syncthreads();

    unsigned long long acc[4][4];
    #pragma unroll
    for(int i = 0; i < 4; i++)
        #pragma unroll
        for(int j = 0; j < 4; j++) acc[i][j] = 0ULL;

    const int NT = KDIM / BK;
    for(int kt = 0; kt < NT; kt++){
        int cur = kt & 1;
        if(kt + 1 < NT){
            const float* Ap = Ap0 + (size_t)(kt+1)*BK;
            ra0 = *(const float4*)(Ap);
            ra1 = *(const float4*)(Ap + (size_t)64*KDIM);
            rb  = *(const float4*)(Bp0 + (size_t)(kt+1)*BK*NDIM);
        }
        #pragma unroll
        for(int k = 0; k < BK; k++){
            const float* asp = &As[cur][k*ASD + mBase];
            ulonglong2 a01 = *(const ulonglong2*)(asp);
            ulonglong2 a23 = *(const ulonglong2*)(asp + 4);
            float4 bv = *(const float4*)&Bs[cur][k*BSD + nBase];
            unsigned long long ar[4] = {a01.x, a01.y, a23.x, a23.y};
            unsigned long long bb[4];
            bb[0] = pk2(bv.x, bv.x);
            bb[1] = pk2(bv.y, bv.y);
            bb[2] = pk2(bv.z, bv.z);
            bb[3] = pk2(bv.w, bv.w);
            #pragma unroll
            for(int i = 0; i < 4; i++)
                #pragma unroll
                for(int j = 0; j < 4; j++)
                    acc[i][j] = ffma2(ar[i], bb[j], acc[i][j]);
        }
        if(kt + 1 < NT){
            int nb = cur ^ 1;
            #pragma unroll
            for(int jj = 0; jj < 4; jj++){
                As[nb][(a_k4*4+jj)*ASD + a_m     ] = ((const float*)&ra0)[jj];
                As[nb][(a_k4*4+jj)*ASD + a_m + 64] = ((const float*)&ra1)[jj];
            }
            *(float4*)&Bs[nb][b_k*BSD + b_n] = rb;
            __syncthreads();
        }
    }

    #pragma unroll
    for(int i = 0; i < 4; i++){
        int m0 = row0 + mBase + 2*i;
        float4 w0, w1;
        unpk2(acc[i][0], w0.x, w1.x);
        unpk2(acc[i][1], w0.y, w1.y);
        unpk2(acc[i][2], w0.z, w1.z);
        unpk2(acc[i][3], w0.w, w1.w);
        int col = col0 + nBase;
        if(EPI){
            float4 d  = *(const float4*)&Dv[col];
            float4 x0 = *(const float4*)&X[(size_t)m0*NDIM + col];
            float4 x1 = *(const float4*)&X[(size_t)(m0+1)*NDIM + col];
            w0.x += x0.x*d.x; w0.y += x0.y*d.y; w0.z += x0.z*d.z; w0.w += x0.w*d.w;
            w1.x += x1.x*d.x; w1.y += x1.y*d.y; w1.z += x1.z*d.z; w1.w += x1.w*d.w;
        }
        *(float4*)&Cout[(size_t)m0*NDIM + col]     = w0;
        *(float4*)&Cout[(size_t)(m0+1)*NDIM + col] = w1;
    }
}

// ---------------- Phase A: local chunk scans from 0, emit finals ------------
__global__ void __launch_bounds__(256) k_scanA(){
    __shared__ unsigned long long h2[DS][4];   // (b,b+1) pairs, 4 pairs
    int c = blockIdx.x, j = threadIdx.x;
    #pragma unroll
    for(int p = 0; p < 4; p++) h2[j][p] = 0ULL;
    __syncthreads();
    unsigned long long acc[4];
    for(int t = 0; t < LCH; t++){
        int tt = c*LCH + t;
        #pragma unroll
        for(int p = 0; p < 4; p++)
            acc[p] = pk2(g_u[((size_t)(2*p)*SEQ   + tt)*DS + j],
                         g_u[((size_t)(2*p+1)*SEQ + tt)*DS + j]);
        #pragma unroll 8
        for(int i = 0; i < DS; i++){
            float a = g_Ad[i*DS + j];
            unsigned long long aa = pk2(a, a);
            acc[0] = ffma2(h2[i][0], aa, acc[0]);
            acc[1] = ffma2(h2[i][1], aa, acc[1]);
            acc[2] = ffma2(h2[i][2], aa, acc[2]);
            acc[3] = ffma2(h2[i][3], aa, acc[3]);
        }
        __syncthreads();
        #pragma unroll
        for(int p = 0; p < 4; p++) h2[j][p] = acc[p];
        __syncthreads();
    }
    #pragma unroll
    for(int p = 0; p < 4; p++){
        float lo, hi; unpk2(acc[p], lo, hi);
        g_f[((2*p)*NCH   + c)*DS + j] = lo;
        g_f[((2*p+1)*NCH + c)*DS + j] = hi;
    }
}

// ---------------- Phase B: Kogge-Stone over chunk boundaries ----------------
__global__ void __launch_bounds__(256) k_ks(int s){
    int c = blockIdx.x, j = threadIdx.x, d = 1 << s;
    const float* In  = (s & 1) ? g_g : g_f;
    float*       Out = (s & 1) ? g_f : g_g;
    const float* P = g_P[s];
    if(c < d){
        #pragma unroll
        for(int b = 0; b < BATCH; b++)
            Out[(b*NCH + c)*DS + j] = In[(b*NCH + c)*DS + j];
        return;
    }
    __shared__ unsigned long long h2[DS][4];
    #pragma unroll
    for(int p = 0; p < 4; p++)
        h2[j][p] = pk2(In[((2*p)*NCH   + c - d)*DS + j],
                       In[((2*p+1)*NCH + c - d)*DS + j]);
    __syncthreads();
    unsigned long long acc[4];
    #pragma unroll
    for(int p = 0; p < 4; p++)
        acc[p] = pk2(In[((2*p)*NCH   + c)*DS + j],
                     In[((2*p+1)*NCH + c)*DS + j]);
    #pragma unroll 8
    for(int i = 0; i < DS; i++){
        float a = P[i*DS + j];
        unsigned long long aa = pk2(a, a);
        acc[0] = ffma2(h2[i][0], aa, acc[0]);
        acc[1] = ffma2(h2[i][1], aa, acc[1]);
        acc[2] = ffma2(h2[i][2], aa, acc[2]);
        acc[3] = ffma2(h2[i][3], aa, acc[3]);
    }
    #pragma unroll
    for(int p = 0; p < 4; p++){
        float lo, hi; unpk2(acc[p], lo, hi);
        Out[((2*p)*NCH   + c)*DS + j] = lo;
        Out[((2*p+1)*NCH + c)*DS + j] = hi;
    }
}

// ---------------- Phase C: replay chunks from boundary states, emit hs ------
__global__ void __launch_bounds__(256) k_scanC(){
    __shared__ unsigned long long h2[DS][4];
    int c = blockIdx.x, j = threadIdx.x;
    if(c == 0){
        #pragma unroll
        for(int p = 0; p < 4; p++) h2[j][p] = 0ULL;
    } else {
        #pragma unroll
        for(int p = 0; p < 4; p++)
            h2[j][p] = pk2(g_g[((2*p)*NCH   + c - 1)*DS + j],
                           g_g[((2*p+1)*NCH + c - 1)*DS + j]);
    }
    __syncthreads();
    unsigned long long acc[4];
    for(int t = 0; t < LCH; t++){
        int tt = c*LCH + t;
        #pragma unroll
        for(int p = 0; p < 4; p++)
            acc[p] = pk2(g_u[((size_t)(2*p)*SEQ   + tt)*DS + j],
                         g_u[((size_t)(2*p+1)*SEQ + tt)*DS + j]);
        #pragma unroll 8
        for(int i = 0; i < DS; i++){
            float a = g_Ad[i*DS + j];
            unsigned long long aa = pk2(a, a);
            acc[0] = ffma2(h2[i][0], aa, acc[0]);
            acc[1] = ffma2(h2[i][1], aa, acc[1]);
            acc[2] = ffma2(h2[i][2], aa, acc[2]);
            acc[3] = ffma2(h2[i][3], aa, acc[3]);
        }
        __syncthreads();
        #pragma unroll
        for(int p = 0; p < 4; p++){
            h2[j][p] = acc[p];
            float lo, hi; unpk2(acc[p], lo, hi);
            g_hs[((size_t)(2*p)*SEQ   + tt)*DS + j] = lo;
            g_hs[((size_t)(2*p+1)*SEQ + tt)*DS + j] = hi;
        }
        __syncthreads();
    }
}

// ---------------- launch ----------------------------------------------------
extern "C" void kernel_launch(void* const* d_in, const int* in_sizes, int n_in,
                              void* d_out, int out_size){
    const float* x  = (const float*)d_in[0];
    const float* A  = (const float*)d_in[1];
    const float* Bm = (const float*)d_in[2];
    const float* Cm = (const float*)d_in[3];
    const float* Dv = (const float*)d_in[4];
    const float* h0 = (const float*)d_in[5];
    float* y = (float*)d_out;

    void* pu  = nullptr;  cudaGetSymbolAddress(&pu,  g_u);
    void* phs = nullptr;  cudaGetSymbolAddress(&phs, g_hs);

    // u = x @ B  (independent of expm chain)
    k_gemm<DM, DS, false><<<dim3(DS/64, MTOT/128), 256>>>(
        x, Bm, (float*)pu, nullptr, nullptr);

    // expm(0.1A) via Taylor (terms 0..8), then powers for the boundary scan
    k_init<<<DS*DS/256, 256>>>(A);
    int src = 1;
    for(int k = 2; k <= 8; k++){
        int dst = (src == 1) ? 2 : 1;
        k_mm256<<<dim3(8,8), 256>>>(src, 0, dst, 1.0f/(float)k, 1);
        src = dst;
    }
    // squarings: T1=Ad^2, T0=Ad^4, T1=Ad^8, P0=Ad^16, P1..P6 by squaring
    k_mm256<<<dim3(8,8), 256>>>(3, 3, 2, 1.0f, 0);
    k_mm256<<<dim3(8,8), 256>>>(2, 2, 1, 1.0f, 0);
    k_mm256<<<dim3(8,8), 256>>>(1, 1, 2, 1.0f, 0);
    k_mm256<<<dim3(8,8), 256>>>(2, 2, 4, 1.0f, 0);
    for(int s = 1; s < 7; s++)
        k_mm256<<<dim3(8,8), 256>>>(3 + s, 3 + s, 4 + s, 1.0f, 0);

    // fold h0 into u (h0 is zero here, but keep it general)
    k_h0<<<1, 256>>>(h0);

    // chunked scan
    k_scanA<<<NCH, 256>>>();
    for(int s = 0; s < 7; s++)
        k_ks<<<NCH, 256>>>(s);
    k_scanC<<<NCH, 256>>>();

    // y = hs @ C + x * D
    k_gemm<DS, DM, true><<<dim3(DM/64, MTOT/128), 256>>>(
        (const float*)phs, Cm, y, x, Dv);
}